// round 8
// baseline (speedup 1.0000x reference)
#include <cuda_runtime.h>
#include <math.h>

#define N_NODES 8000
#define NT      (N_NODES * 12)        // 96000
#define NODES_PER_BLK 64
#define NBLOCKS 125                   // 8000/64
#define NTHREADS 320

// Row-per-block partials: g_part[b][j]; rows 125..127 never written (stay 0.0
// from static zero-init) -> last-block combine sums a fixed 128 rows, fixed order.
__device__ float    g_part[128][128];
__device__ float    gAt2[144];        // At2[t1*12+t2]
__device__ unsigned g_tick;           // monotonic ticket (never reset; +125/replay)

// ===================== k1: partials + last-block At2 =====================
__global__ void __launch_bounds__(NTHREADS)
partials_kernel(const float* __restrict__ x,
                const float* __restrict__ U1,
                const float* __restrict__ U2,   // (5,8000) row-major
                const float* __restrict__ U3,
                const float* __restrict__ be,
                const float* __restrict__ Ve)
{
    __shared__ float sX [NODES_PER_BLK][61];    // x[nl][t*5+f], pad 61
    __shared__ float sRhs[NODES_PER_BLK][13];
    __shared__ float sU1[NODES_PER_BLK];
    __shared__ float sU2[5][NODES_PER_BLK];
    __shared__ float sU3[5];
    __shared__ float sQ[2][120];
    __shared__ float sLhs[60];
    __shared__ float sM2[60];
    __shared__ int   sLast;

    const int tid = threadIdx.x;
    const int b   = blockIdx.x;
    const int n0  = b * NODES_PER_BLK;

    // coalesced x tile load: 960 float4, 3 rounds
    {
        const float4* xp = (const float4*)(x + n0 * 60);
        #pragma unroll
        for (int r = 0; r < 3; r++) {
            const int j = tid + r * NTHREADS;
            float4 v = xp[j];
            const int n = j / 15, c = (j % 15) * 4;
            float* d = &sX[n][c];
            d[0] = v.x; d[1] = v.y; d[2] = v.z; d[3] = v.w;
        }
    }
    if (tid < NODES_PER_BLK) sU1[tid] = U1[n0 + tid];
    if (tid < 5)             sU3[tid] = U3[tid];
    {
        const int f2 = tid / NODES_PER_BLK, nl = tid % NODES_PER_BLK;  // all 320
        sU2[f2][nl] = U2[f2 * N_NODES + n0 + nl];
    }
    __syncthreads();

    // rhs[nl][t] = sum_f x*U3
    for (int j = tid; j < NODES_PER_BLK * 12; j += NTHREADS) {
        const int nl = j / 12, t = j % 12;
        float r = 0.f;
        #pragma unroll
        for (int f = 0; f < 5; f++) r += sX[nl][t * 5 + f] * sU3[f];
        sRhs[nl][t] = r;
    }
    __syncthreads();

    // block partials: j<60 lhs[t*5+f], 60..119 M2[f2*12+t]
    if (tid < 120) {
        float acc = 0.f;
        if (tid < 60) {
            #pragma unroll 8
            for (int nl = 0; nl < NODES_PER_BLK; nl++)
                acc += sX[nl][tid] * sU1[nl];
        } else {
            const int jj = tid - 60;
            const int f2 = jj / 12, t = jj % 12;
            #pragma unroll 8
            for (int nl = 0; nl < NODES_PER_BLK; nl++)
                acc += sU2[f2][nl] * sRhs[nl][t];
        }
        g_part[b][tid] = acc;            // coalesced 120-float row
    }
    __syncthreads();                     // order STGs before ticket

    if (tid == 0) {
        __threadfence();                 // release partials to L2
        unsigned old = atomicAdd(&g_tick, 1u);
        sLast = ((old + 1u) % (unsigned)NBLOCKS == 0u) ? 1 : 0;
    }
    __syncthreads();
    if (!sLast) return;                  // everyone except the last block exits

    // ---- last block only: combine (fixed order) + At2 ----
    __threadfence();                     // acquire
    if (tid < 240) {
        const int q = tid / 120, j = tid % 120;
        const float* p = &g_part[q * 64][0];
        float s = 0.f;
        #pragma unroll 16
        for (int i = 0; i < 64; i++)
            s += __ldcg(p + i * 128 + j);       // rows 125..127 read as 0
        sQ[q][j] = s;
    }
    __syncthreads();
    if (tid < 120) {
        float s = sQ[0][tid] + sQ[1][tid];
        if (tid < 60) sLhs[tid] = s;
        else          sM2[tid - 60] = s;
    }
    __syncthreads();

    if (tid < 12) {                      // lane t2 owns a column
        const int t2 = tid;
        float S[12];
        #pragma unroll
        for (int t1 = 0; t1 < 12; t1++) {
            float p = 0.f;
            #pragma unroll
            for (int f = 0; f < 5; f++) p += sLhs[t1 * 5 + f] * sM2[f * 12 + t2];
            p += be[t1 * 12 + t2];
            S[t1] = 1.f / (1.f + expf(-p));
        }
        float E[12];
        #pragma unroll
        for (int t1 = 0; t1 < 12; t1++) {
            float e = 0.f;
            #pragma unroll
            for (int k = 0; k < 12; k++) e += Ve[t1 * 12 + k] * S[k];   // lane-uniform
            E[t1] = e;
        }
        float mx = -1e30f;
        #pragma unroll
        for (int k = 0; k < 12; k++) mx = fmaxf(mx, E[k]);
        float den = 0.f;
        #pragma unroll
        for (int k = 0; k < 12; k++) { E[k] = expf(E[k] - mx); den += E[k]; }
        const float inv = 1.f / den;
        #pragma unroll
        for (int k = 0; k < 12; k++) gAt2[k * 12 + t2] = E[k] * inv;
    }
    // kernel end = implicit full release; k2 sees gAt2 at launch boundary
}

// ========================= k2: apply At2 + conv =========================
__global__ void __launch_bounds__(NTHREADS)
apply_kernel(const float* __restrict__ x,
             const float* __restrict__ w,     // conv2_w (5,5,1,3)
             const float* __restrict__ bias,  // conv2_b (5,)
             float* __restrict__ out)
{
    __shared__ float sX [NODES_PER_BLK][61];
    __shared__ float sX2[5][NODES_PER_BLK * 13];
    __shared__ float sAt[12][12];
    __shared__ float sW[75];
    __shared__ float sB[5];

    const int tid = threadIdx.x;
    const int n0  = blockIdx.x * NODES_PER_BLK;

    // x tile: L2-hot (k1 just streamed it) -> ~250cyc hits
    {
        const float4* xp = (const float4*)(x + n0 * 60);
        #pragma unroll
        for (int r = 0; r < 3; r++) {
            const int j = tid + r * NTHREADS;
            float4 v = xp[j];
            const int n = j / 15, c = (j % 15) * 4;
            float* d = &sX[n][c];
            d[0] = v.x; d[1] = v.y; d[2] = v.z; d[3] = v.w;
        }
    }
    if (tid < 144) sAt[tid / 12][tid % 12] = gAt2[tid];
    if (tid >= 160 && tid < 235) sW[tid - 160] = w[tid - 160];
    if (tid >= 256 && tid < 261) sB[tid - 256] = bias[tid - 256];
    __syncthreads();

    // Phase B: thread (f, nl) -> x2[f][nl][0..11]
    {
        const int f  = tid / NODES_PER_BLK;
        const int nl = tid % NODES_PER_BLK;
        float xr[12];
        #pragma unroll
        for (int tp = 0; tp < 12; tp++) xr[tp] = sX[nl][tp * 5 + f];
        float* dst = &sX2[f][nl * 13];
        #pragma unroll
        for (int t = 0; t < 12; t++) {
            float a = 0.f;
            #pragma unroll
            for (int tp = 0; tp < 12; tp++) a += xr[tp] * sAt[tp][t];
            dst[t] = a;
        }
    }
    __syncthreads();

    // Phase C: thread (o, nl) -> conv plane + coalesced 48B store
    {
        const int o  = tid / NODES_PER_BLK;
        const int nl = tid % NODES_PER_BLK;
        float wr[15];
        #pragma unroll
        for (int i = 0; i < 15; i++) wr[i] = sW[o * 15 + i];
        const float b0 = sB[o];

        float yr[12];
        #pragma unroll
        for (int t = 0; t < 12; t++) yr[t] = b0;
        #pragma unroll
        for (int fi = 0; fi < 5; fi++) {
            const float* s = &sX2[fi][nl * 13];
            float v[12];
            #pragma unroll
            for (int t = 0; t < 12; t++) v[t] = s[t];
            const float w0 = wr[fi * 3 + 0], w1 = wr[fi * 3 + 1], w2 = wr[fi * 3 + 2];
            #pragma unroll
            for (int t = 0; t < 12; t++) {
                float a = w1 * v[t];
                if (t > 0)  a += w0 * v[t - 1];
                if (t < 11) a += w2 * v[t + 1];
                yr[t] += a;
            }
        }
        // raw-reshape output: flat = o*N*T + n*T + t
        float4* op = (float4*)(out + o * NT + (n0 + nl) * 12);
        op[0] = make_float4(yr[0], yr[1], yr[2],  yr[3]);
        op[1] = make_float4(yr[4], yr[5], yr[6],  yr[7]);
        op[2] = make_float4(yr[8], yr[9], yr[10], yr[11]);
    }
}

extern "C" void kernel_launch(void* const* d_in, const int* in_sizes, int n_in,
                              void* d_out, int out_size)
{
    // metadata order: x, adj, U1_1, U2_1, U3_1, be_1, Ve_1,
    //                 U1_2, U2_2, U3_2, be_2, Ve_2,
    //                 conv1_w, conv1_b, conv2_w, conv2_b, W_hgc, b_hgc
    const float* x    = (const float*)d_in[0];
    const float* U1_2 = (const float*)d_in[7];
    const float* U2_2 = (const float*)d_in[8];
    const float* U3_2 = (const float*)d_in[9];
    const float* be_2 = (const float*)d_in[10];
    const float* Ve_2 = (const float*)d_in[11];
    const float* c2w  = (const float*)d_in[14];
    const float* c2b  = (const float*)d_in[15];
    float* out = (float*)d_out;

    // Hyperbolic branch contributes exactly 0.0*finite -> skipped entirely.
    partials_kernel<<<NBLOCKS, NTHREADS>>>(x, U1_2, U2_2, U3_2, be_2, Ve_2);
    apply_kernel<<<NBLOCKS, NTHREADS>>>(x, c2w, c2b, out);
}

// round 9
// speedup vs baseline: 1.0276x; 1.0276x over previous
#include <cuda_runtime.h>
#include <math.h>

#define N_NODES 8000
#define NT      (N_NODES * 12)        // 96000

// ---- k1 (reduce) config ----
#define NBLK_R  100                   // reduce blocks
#define CHUNK_R (N_NODES / NBLK_R)    // 80 nodes/block
#define SUBG    4                     // subgroups of 128 threads
#define SUBCH   (CHUNK_R / SUBG)      // 20 nodes/subgroup

// ---- k2 (apply) config ----
#define NODES_PER_BLK 64
#define NBLK_M  (N_NODES / NODES_PER_BLK)   // 125
#define NTHREADS 320

// Row-per-block partials: g_part[b][j]; rows 100..127 never written (stay 0.0
// from static zero-init) -> last-block combine sums a fixed 128 rows, fixed order.
__device__ float    g_part[128][128];
__device__ float    gAt2[144];        // At2[t1*12+t2]
__device__ unsigned g_tick;           // monotonic ticket (+100/replay, never reset)

// ============ k1: lean reduce + last-block At2 (no spins) ============
__global__ void __launch_bounds__(SUBG * 128)
reduce_kernel(const float* __restrict__ x,
              const float* __restrict__ U1,
              const float* __restrict__ U2,   // (5,8000) row-major
              const float* __restrict__ U3,
              const float* __restrict__ be,
              const float* __restrict__ Ve)
{
    __shared__ float sAcc[SUBG][128];
    __shared__ float sQ[2][120];
    __shared__ float sLhs[60];
    __shared__ float sM2[60];
    __shared__ int   sLast;

    const int tid = threadIdx.x;
    const int j   = tid & 127;            // 0..127 (use <120)
    const int g   = tid >> 7;             // 0..3
    const int b   = blockIdx.x;
    const int n0  = b * CHUNK_R + g * SUBCH;

    float acc = 0.f;
    if (j < 60) {
        // lhs_tf[t*5+f] partial: coalesced across threads 0..59 per node row
        #pragma unroll
        for (int i = 0; i < SUBCH; i++) {
            const int n = n0 + i;
            acc += x[n * 60 + j] * U1[n];
        }
    } else if (j < 120) {
        const int jj = j - 60;
        const int f2 = jj / 12;
        const int t  = jj % 12;
        float u3[5];
        #pragma unroll
        for (int f = 0; f < 5; f++) u3[f] = U3[f];
        #pragma unroll
        for (int i = 0; i < SUBCH; i++) {
            const int n = n0 + i;
            float r = 0.f;
            #pragma unroll
            for (int f = 0; f < 5; f++)
                r += x[n * 60 + t * 5 + f] * u3[f];   // same lines as lhs warps (L1 hit)
            acc += U2[f2 * N_NODES + n] * r;          // 12-thread broadcast
        }
    }
    sAcc[g][j] = acc;
    __syncthreads();

    if (g == 0 && j < 120) {
        // fixed-order subgroup combine -> coalesced 120-float row
        g_part[b][j] = sAcc[0][j] + sAcc[1][j] + sAcc[2][j] + sAcc[3][j];
    }
    __syncthreads();                      // order STG before ticket

    if (tid == 0) {
        __threadfence();                  // release partials to L2
        unsigned old = atomicAdd(&g_tick, 1u);
        sLast = ((old + 1u) % (unsigned)NBLK_R == 0u) ? 1 : 0;
    }
    __syncthreads();
    if (!sLast) return;                   // no spinning: everyone else exits

    // ---- last block only: combine all partials (fixed order) + At2 ----
    __threadfence();                      // acquire
    if (tid < 240) {
        const int q = tid / 120, jj = tid % 120;
        const float* p = &g_part[q * 64][0];
        float s = 0.f;
        #pragma unroll 16
        for (int i = 0; i < 64; i++)
            s += __ldcg(p + i * 128 + jj);            // rows 100..127 read as 0
        sQ[q][jj] = s;
    }
    __syncthreads();
    if (tid < 120) {
        float s = sQ[0][tid] + sQ[1][tid];
        if (tid < 60) sLhs[tid] = s;
        else          sM2[tid - 60] = s;
    }
    __syncthreads();

    if (tid < 12) {                       // lane t2 owns a column of At2
        const int t2 = tid;
        float S[12];
        #pragma unroll
        for (int t1 = 0; t1 < 12; t1++) {
            float p = 0.f;
            #pragma unroll
            for (int f = 0; f < 5; f++) p += sLhs[t1 * 5 + f] * sM2[f * 12 + t2];
            p += be[t1 * 12 + t2];
            S[t1] = 1.f / (1.f + expf(-p));
        }
        float E[12];
        #pragma unroll
        for (int t1 = 0; t1 < 12; t1++) {
            float e = 0.f;
            #pragma unroll
            for (int k = 0; k < 12; k++) e += Ve[t1 * 12 + k] * S[k];   // lane-uniform
            E[t1] = e;
        }
        float mx = -1e30f;
        #pragma unroll
        for (int k = 0; k < 12; k++) mx = fmaxf(mx, E[k]);
        float den = 0.f;
        #pragma unroll
        for (int k = 0; k < 12; k++) { E[k] = expf(E[k] - mx); den += E[k]; }
        const float inv = 1.f / den;
        #pragma unroll
        for (int k = 0; k < 12; k++) gAt2[k * 12 + t2] = E[k] * inv;
    }
    // kernel-end = full release; launch boundary orders gAt2 for k2
}

// ========================= k2: apply At2 + conv =========================
__global__ void __launch_bounds__(NTHREADS)
apply_kernel(const float* __restrict__ x,
             const float* __restrict__ w,     // conv2_w (5,5,1,3)
             const float* __restrict__ bias,  // conv2_b (5,)
             float* __restrict__ out)
{
    __shared__ float sX [NODES_PER_BLK][61];
    __shared__ float sX2[5][NODES_PER_BLK * 13];
    __shared__ float sAt[12][12];
    __shared__ float sW[75];
    __shared__ float sB[5];

    const int tid = threadIdx.x;
    const int n0  = blockIdx.x * NODES_PER_BLK;

    // x tile: L2-hot (k1 just streamed it)
    {
        const float4* xp = (const float4*)(x + n0 * 60);
        #pragma unroll
        for (int r = 0; r < 3; r++) {
            const int j = tid + r * NTHREADS;
            float4 v = xp[j];
            const int n = j / 15, c = (j % 15) * 4;
            float* d = &sX[n][c];
            d[0] = v.x; d[1] = v.y; d[2] = v.z; d[3] = v.w;
        }
    }
    if (tid < 144) sAt[tid / 12][tid % 12] = gAt2[tid];
    if (tid >= 160 && tid < 235) sW[tid - 160] = w[tid - 160];
    if (tid >= 256 && tid < 261) sB[tid - 256] = bias[tid - 256];
    __syncthreads();

    // Phase B: thread (f, nl) -> x2[f][nl][0..11]
    {
        const int f  = tid / NODES_PER_BLK;
        const int nl = tid % NODES_PER_BLK;
        float xr[12];
        #pragma unroll
        for (int tp = 0; tp < 12; tp++) xr[tp] = sX[nl][tp * 5 + f];
        float* dst = &sX2[f][nl * 13];
        #pragma unroll
        for (int t = 0; t < 12; t++) {
            float a = 0.f;
            #pragma unroll
            for (int tp = 0; tp < 12; tp++) a += xr[tp] * sAt[tp][t];
            dst[t] = a;
        }
    }
    __syncthreads();

    // Phase C: thread (o, nl) -> conv plane + coalesced 48B store
    {
        const int o  = tid / NODES_PER_BLK;
        const int nl = tid % NODES_PER_BLK;
        float wr[15];
        #pragma unroll
        for (int i = 0; i < 15; i++) wr[i] = sW[o * 15 + i];
        const float b0 = sB[o];

        float yr[12];
        #pragma unroll
        for (int t = 0; t < 12; t++) yr[t] = b0;
        #pragma unroll
        for (int fi = 0; fi < 5; fi++) {
            const float* s = &sX2[fi][nl * 13];
            float v[12];
            #pragma unroll
            for (int t = 0; t < 12; t++) v[t] = s[t];
            const float w0 = wr[fi * 3 + 0], w1 = wr[fi * 3 + 1], w2 = wr[fi * 3 + 2];
            #pragma unroll
            for (int t = 0; t < 12; t++) {
                float a = w1 * v[t];
                if (t > 0)  a += w0 * v[t - 1];
                if (t < 11) a += w2 * v[t + 1];
                yr[t] += a;
            }
        }
        // raw-reshape output: flat = o*N*T + n*T + t
        float4* op = (float4*)(out + o * NT + (n0 + nl) * 12);
        op[0] = make_float4(yr[0], yr[1], yr[2],  yr[3]);
        op[1] = make_float4(yr[4], yr[5], yr[6],  yr[7]);
        op[2] = make_float4(yr[8], yr[9], yr[10], yr[11]);
    }
}

extern "C" void kernel_launch(void* const* d_in, const int* in_sizes, int n_in,
                              void* d_out, int out_size)
{
    // metadata order: x, adj, U1_1, U2_1, U3_1, be_1, Ve_1,
    //                 U1_2, U2_2, U3_2, be_2, Ve_2,
    //                 conv1_w, conv1_b, conv2_w, conv2_b, W_hgc, b_hgc
    const float* x    = (const float*)d_in[0];
    const float* U1_2 = (const float*)d_in[7];
    const float* U2_2 = (const float*)d_in[8];
    const float* U3_2 = (const float*)d_in[9];
    const float* be_2 = (const float*)d_in[10];
    const float* Ve_2 = (const float*)d_in[11];
    const float* c2w  = (const float*)d_in[14];
    const float* c2b  = (const float*)d_in[15];
    float* out = (float*)d_out;

    // Hyperbolic branch contributes exactly 0.0*finite -> skipped entirely.
    reduce_kernel<<<NBLK_R, SUBG * 128>>>(x, U1_2, U2_2, U3_2, be_2, Ve_2);
    apply_kernel<<<NBLK_M, NTHREADS>>>(x, c2w, c2b, out);
}

// round 10
// speedup vs baseline: 1.2851x; 1.2505x over previous
#include <cuda_runtime.h>
#include <math.h>

#define N_NODES 8000
#define NT      (N_NODES * 12)        // 96000
#define NODES_PER_BLK 64
#define NBLOCKS 125                   // 8000/64, <=148 SMs -> all co-resident
#define NTHREADS 320

// Row-per-block partials: g_part[b][j]; rows 125..127 never written (stay 0.0
// from static zero-init) -> combine sums a fixed 128 rows in fixed order.
__device__ float    g_part[128][128];
__device__ unsigned g_arrive;         // monotonic epoch counter (never reset)

__global__ void __launch_bounds__(NTHREADS)
fused_kernel(const float* __restrict__ x,
             const float* __restrict__ U1,
             const float* __restrict__ U2,   // (5,8000) row-major
             const float* __restrict__ U3,
             const float* __restrict__ be,
             const float* __restrict__ Ve,
             const float* __restrict__ w,    // conv2_w (5,5,1,3) flat o*15+i*3+k
             const float* __restrict__ bias, // conv2_b (5,)
             float* __restrict__ out)
{
    __shared__ float sX [NODES_PER_BLK][61];      // x[nl][t*5+f], pad 61
    __shared__ float sRhs[NODES_PER_BLK][13];
    __shared__ float sX2[5][NODES_PER_BLK * 13];
    __shared__ float sQ[2][120];
    __shared__ float sU1[NODES_PER_BLK];
    __shared__ float sU2[5][NODES_PER_BLK];
    __shared__ float sU3[5];
    __shared__ float sVe[144];
    __shared__ float sLhs[60];
    __shared__ float sM2[60];
    __shared__ float sAt[12][12];
    __shared__ float sW[75];
    __shared__ float sB[5];

    const int tid = threadIdx.x;
    const int b   = blockIdx.x;
    const int n0  = b * NODES_PER_BLK;

    // ---- Coalesced x-tile load: 960 float4, 3 rounds ----
    {
        const float4* xp = (const float4*)(x + n0 * 60);
        #pragma unroll
        for (int r = 0; r < 3; r++) {
            const int j = tid + r * NTHREADS;
            float4 v = xp[j];
            const int n = j / 15, c = (j % 15) * 4;
            float* d = &sX[n][c];
            d[0] = v.x; d[1] = v.y; d[2] = v.z; d[3] = v.w;
        }
    }
    if (tid < NODES_PER_BLK) sU1[tid] = U1[n0 + tid];
    if (tid < 5)             sU3[tid] = U3[tid];
    {
        const int f2 = tid / NODES_PER_BLK, nl = tid % NODES_PER_BLK;  // all 320
        sU2[f2][nl] = U2[f2 * N_NODES + n0 + nl];
    }
    if (tid >= 64 && tid < 139)  sW[tid - 64]  = w[tid - 64];
    if (tid >= 160 && tid < 165) sB[tid - 160] = bias[tid - 160];
    __syncthreads();

    // ---- rhs[nl][t] = sum_f x*U3 ----
    for (int j = tid; j < NODES_PER_BLK * 12; j += NTHREADS) {
        const int nl = j / 12, t = j % 12;
        float r = 0.f;
        #pragma unroll
        for (int f = 0; f < 5; f++) r += sX[nl][t * 5 + f] * sU3[f];
        sRhs[nl][t] = r;
    }
    __syncthreads();

    // ---- Block partials (120 threads); idle threads prefetch Ve ----
    if (tid < 120) {
        float acc = 0.f;
        if (tid < 60) {
            #pragma unroll 8
            for (int nl = 0; nl < NODES_PER_BLK; nl++)
                acc += sX[nl][tid] * sU1[nl];
        } else {
            const int jj = tid - 60;
            const int f2 = jj / 12, t = jj % 12;
            #pragma unroll 8
            for (int nl = 0; nl < NODES_PER_BLK; nl++)
                acc += sU2[f2][nl] * sRhs[nl][t];
        }
        g_part[b][tid] = acc;            // coalesced 120-float row
    } else if (tid >= 128 && tid < 272) {
        sVe[tid - 128] = Ve[tid - 128];  // overlap with partials
    }
    __syncthreads();                     // order STGs before release fence

    // ---- Grid barrier: single release fence + monotonic epoch spin ----
    if (tid == 0) {
        __threadfence();                 // release partials (one MEMBAR.GPU)
        unsigned old = atomicAdd(&g_arrive, 1u);
        const unsigned target = (old / (unsigned)NBLOCKS + 1u) * (unsigned)NBLOCKS;
        volatile unsigned* va = &g_arrive;
        while (*va < target) { }
        __threadfence();                 // acquire
    }
    __syncthreads();

    // ---- Combine: (half q, j) sums 64 rows, warp-coalesced, fixed order ----
    if (tid < 240) {
        const int q = tid / 120, j = tid % 120;
        const float* p = &g_part[q * 64][0];
        float s = 0.f;
        #pragma unroll 16
        for (int i = 0; i < 64; i++)
            s += __ldcg(p + i * 128 + j);          // rows 125..127 read as 0
        sQ[q][j] = s;
    }
    __syncthreads();
    if (tid < 120) {
        float s = sQ[0][tid] + sQ[1][tid];
        if (tid < 60) sLhs[tid] = s;
        else          sM2[tid - 60] = s;
    }
    __syncthreads();

    // ---- At2 in warp 0: lane t2 owns a column ----
    if (tid < 12) {
        const int t2 = tid;
        float S[12];
        #pragma unroll
        for (int t1 = 0; t1 < 12; t1++) {
            float p = 0.f;
            #pragma unroll
            for (int f = 0; f < 5; f++) p += sLhs[t1 * 5 + f] * sM2[f * 12 + t2];
            p += be[t1 * 12 + t2];
            S[t1] = 1.f / (1.f + __expf(-p));
        }
        float E[12];
        #pragma unroll
        for (int t1 = 0; t1 < 12; t1++) {
            float e = 0.f;
            #pragma unroll
            for (int k = 0; k < 12; k++) e += sVe[t1 * 12 + k] * S[k];
            E[t1] = e;
        }
        float mx = -1e30f;
        #pragma unroll
        for (int k = 0; k < 12; k++) mx = fmaxf(mx, E[k]);
        float den = 0.f;
        #pragma unroll
        for (int k = 0; k < 12; k++) { E[k] = __expf(E[k] - mx); den += E[k]; }
        const float inv = 1.f / den;
        #pragma unroll
        for (int k = 0; k < 12; k++) sAt[k][t2] = E[k] * inv;
    }
    __syncthreads();

    // ---- Phase B: thread (f, nl) -> x2[f][nl][0..11] ----
    {
        const int f  = tid / NODES_PER_BLK;
        const int nl = tid % NODES_PER_BLK;
        float xr[12];
        #pragma unroll
        for (int tp = 0; tp < 12; tp++) xr[tp] = sX[nl][tp * 5 + f];
        float* dst = &sX2[f][nl * 13];
        #pragma unroll
        for (int t = 0; t < 12; t++) {
            float a = 0.f;
            #pragma unroll
            for (int tp = 0; tp < 12; tp++) a += xr[tp] * sAt[tp][t];
            dst[t] = a;
        }
    }
    __syncthreads();

    // ---- Phase C: thread (o, nl) -> conv plane + coalesced 48B store ----
    {
        const int o  = tid / NODES_PER_BLK;
        const int nl = tid % NODES_PER_BLK;
        float wr[15];
        #pragma unroll
        for (int i = 0; i < 15; i++) wr[i] = sW[o * 15 + i];
        const float b0 = sB[o];

        float yr[12];
        #pragma unroll
        for (int t = 0; t < 12; t++) yr[t] = b0;
        #pragma unroll
        for (int fi = 0; fi < 5; fi++) {
            const float* s = &sX2[fi][nl * 13];
            float v[12];
            #pragma unroll
            for (int t = 0; t < 12; t++) v[t] = s[t];
            const float w0 = wr[fi * 3 + 0], w1 = wr[fi * 3 + 1], w2 = wr[fi * 3 + 2];
            #pragma unroll
            for (int t = 0; t < 12; t++) {
                float a = w1 * v[t];
                if (t > 0)  a += w0 * v[t - 1];
                if (t < 11) a += w2 * v[t + 1];
                yr[t] += a;
            }
        }
        // raw-reshape output: flat = o*N*T + n*T + t
        float4* op = (float4*)(out + o * NT + (n0 + nl) * 12);
        op[0] = make_float4(yr[0], yr[1], yr[2],  yr[3]);
        op[1] = make_float4(yr[4], yr[5], yr[6],  yr[7]);
        op[2] = make_float4(yr[8], yr[9], yr[10], yr[11]);
    }
}

extern "C" void kernel_launch(void* const* d_in, const int* in_sizes, int n_in,
                              void* d_out, int out_size)
{
    // metadata order: x, adj, U1_1, U2_1, U3_1, be_1, Ve_1,
    //                 U1_2, U2_2, U3_2, be_2, Ve_2,
    //                 conv1_w, conv1_b, conv2_w, conv2_b, W_hgc, b_hgc
    const float* x    = (const float*)d_in[0];
    const float* U1_2 = (const float*)d_in[7];
    const float* U2_2 = (const float*)d_in[8];
    const float* U3_2 = (const float*)d_in[9];
    const float* be_2 = (const float*)d_in[10];
    const float* Ve_2 = (const float*)d_in[11];
    const float* c2w  = (const float*)d_in[14];
    const float* c2b  = (const float*)d_in[15];
    float* out = (float*)d_out;

    // Hyperbolic branch contributes exactly 0.0*finite -> skipped entirely.
    fused_kernel<<<NBLOCKS, NTHREADS>>>(x, U1_2, U2_2, U3_2, be_2, Ve_2, c2w, c2b, out);
}